// round 14
// baseline (speedup 1.0000x reference)
#include <cuda_runtime.h>
#include <math.h>
#include <stdint.h>

#define NN 13627
#define EE 504378
#define E2T (EE + NN)

// ---------------- scratch (static device globals; no allocation) ----------------
__device__ float    g_h1 [NN * 300];    // h1 fp32 (GEMM converts A-frags in-kernel)
__device__ uint32_t g_wtf [460000];     // all weights as tf32 bits
__device__ float g_xl1[NN * 300];
__device__ float g_xr1[NN * 300];
__device__ float g_xl2[NN * 100];
__device__ float g_xr2[NN * 100];
__device__ float g_lin1[NN * 100];
__device__ float g_lin2[NN * 100];
__device__ uint32_t g_zb[NN * 50];      // z as bf16x2 (loss-only consumer)
__device__ float g_xl3[NN];
__device__ float g_xr3[NN];
__device__ int   g_deg[NN];
__device__ int   g_off[NN + 1];
__device__ int   g_cur[NN];
__device__ int   g_src[E2T];
__device__ float g_loss[2];

// weight offsets inside g_wtf
#define OFF_WL1   0
#define OFF_WR1   150000
#define OFF_WLIN1 300000
#define OFF_WLIN2 350000
#define OFF_WL2   400000
#define OFF_WR2   430000

__device__ __forceinline__ uint32_t f2tf32(float f) {
    uint32_t o;
    asm("cvt.rna.tf32.f32 %0, %1;" : "=r"(o) : "f"(f));
    return o;
}

// pack two floats into bf16x2 bits (lo = first arg, hi = second)
__device__ __forceinline__ uint32_t pack_bf16x2(float lo, float hi) {
    uint32_t o;
    asm("cvt.rn.bf16x2.f32 %0, %1, %2;" : "=r"(o) : "f"(hi), "f"(lo));
    return o;
}
// exact bf16->fp32 widening via bit ops
__device__ __forceinline__ float bf16lo(uint32_t v) { return __uint_as_float(v << 16); }
__device__ __forceinline__ float bf16hi(uint32_t v) { return __uint_as_float(v & 0xffff0000u); }

// ---------------- tf32 conversion: weights only, 6 segments ----------------
struct CSeg { const float* src; uint32_t* dst; int n4; };  // n4 = n/4

__global__ void conv_weights(CSeg c0, CSeg c1, CSeg c2, CSeg c3, CSeg c4, CSeg c5) {
    int i = blockIdx.x * blockDim.x + threadIdx.x;
    CSeg segs[6] = {c0, c1, c2, c3, c4, c5};
#pragma unroll
    for (int j = 0; j < 6; j++) {
        if (i < segs[j].n4) {
            float4 v = reinterpret_cast<const float4*>(segs[j].src)[i];
            uint4 o;
            o.x = f2tf32(v.x); o.y = f2tf32(v.y);
            o.z = f2tf32(v.z); o.w = f2tf32(v.w);
            reinterpret_cast<uint4*>(segs[j].dst)[i] = o;
        }
    }
}

// ---------------- utility kernels ----------------
__global__ void zero_kernel(int* deg, int* cur, float* loss) {
    int i = blockIdx.x * blockDim.x + threadIdx.x;
    if (i < NN) { deg[i] = 0; cur[i] = 0; }
    if (i < 2) loss[i] = 0.f;
}

__global__ void hist_kernel(const int* __restrict__ ei, int* __restrict__ deg) {
    int k = blockIdx.x * blockDim.x + threadIdx.x;
    if (k >= E2T) return;
    int d = (k < EE) ? ei[EE + k] : (k - EE);
    atomicAdd(&deg[d], 1);
}

__global__ void scan_kernel(const int* __restrict__ deg, int* __restrict__ off) {
    __shared__ int sdata[1024];
    const int n = NN;
    int tid = threadIdx.x;
    const int per = (n + 1023) / 1024;  // 14
    int start = tid * per;
    int vals[16];
    int local = 0;
    for (int i = 0; i < per; i++) {
        int idx = start + i;
        int v = (idx < n) ? deg[idx] : 0;
        vals[i] = local;
        local += v;
    }
    sdata[tid] = local;
    __syncthreads();
    for (int ofs = 1; ofs < 1024; ofs <<= 1) {
        int v = (tid >= ofs) ? sdata[tid - ofs] : 0;
        __syncthreads();
        sdata[tid] += v;
        __syncthreads();
    }
    int base = (tid == 0) ? 0 : sdata[tid - 1];
    for (int i = 0; i < per; i++) {
        int idx = start + i;
        if (idx < n) off[idx] = base + vals[i];
    }
    if (tid == 0) off[n] = sdata[1023];
}

__global__ void scatter_kernel(const int* __restrict__ ei, int* __restrict__ cur,
                               const int* __restrict__ off, int* __restrict__ ssrc) {
    int k = blockIdx.x * blockDim.x + threadIdx.x;
    if (k >= E2T) return;
    int s, d;
    if (k < EE) { s = ei[k]; d = ei[EE + k]; }
    else        { s = d = k - EE; }
    int pos = off[d] + atomicAdd(&cur[d], 1);
    ssrc[pos] = s;
}

// ---------------- TF32 GEMM: fp32 A (cvt on frag load), tf32 B, BM=192 ----------------
#define BM 192
#define BN 64
#define BK 16
#define AS_STRIDE 20
#define BS_STRIDE 72

struct GSeg {
    const uint32_t* B;   // tf32 bits [K,N]
    const float* bias;
    float* C;
    int N;
    int act;
    int blk0;
};

__device__ __forceinline__ void cpa16(uint32_t dst, const void* src, int sz) {
    asm volatile("cp.async.ca.shared.global [%0], [%1], 16, %2;\n"
                 :: "r"(dst), "l"(src), "r"(sz));
}

__global__ __launch_bounds__(256) void gemm_tf32_multi(
    const float* __restrict__ A, int M, int K,
    GSeg s0, GSeg s1, GSeg s2, GSeg s3, int nseg)
{
    __shared__ uint32_t As[2][BM][AS_STRIDE];   // raw fp32 bits of A
    __shared__ uint32_t Bs[2][BK][BS_STRIDE];   // tf32 bits of B

    GSeg sg = s0;
    if (nseg > 1 && (int)blockIdx.x >= s1.blk0) sg = s1;
    if (nseg > 2 && (int)blockIdx.x >= s2.blk0) sg = s2;
    if (nseg > 3 && (int)blockIdx.x >= s3.blk0) sg = s3;
    const uint32_t* B = sg.B;
    int N = sg.N;

    int tid  = threadIdx.x;
    int warp = tid >> 5, lane = tid & 31;
    int warp_m = warp & 3;            // 4 warps along M, 48 rows each
    int warp_n = warp >> 2;           // 2 warps along N, 32 cols each
    int row0 = blockIdx.y * BM;
    int col0 = ((int)blockIdx.x - sg.blk0) * BN;
    int qr = lane >> 2;
    int qc = lane & 3;

    int ar = tid >> 2;                // 0..63
    int ac = (tid & 3) * 4;           // 0,4,8,12
    int br = tid >> 4;                // 0..15
    int bc = (tid & 15) * 4;          // 0..60

    uint32_t as_base = (uint32_t)__cvta_generic_to_shared(&As[0][0][0]);
    uint32_t bs_base = (uint32_t)__cvta_generic_to_shared(&Bs[0][0][0]);
    const uint32_t asbuf = BM * AS_STRIDE * 4;
    const uint32_t bsbuf = BK * BS_STRIDE * 4;

    int ntiles = (K + BK - 1) / BK;

    float c[3][4][4];
#pragma unroll
    for (int mi = 0; mi < 3; mi++)
#pragma unroll
        for (int nj = 0; nj < 4; nj++)
#pragma unroll
            for (int q = 0; q < 4; q++) c[mi][nj][q] = 0.f;

    auto load_tile = [&](int t, int buf) {
        int k0 = t * BK;
#pragma unroll
        for (int h = 0; h < 3; h++) {           // 192 rows = 3 x 64
            int r  = ar + h * 64;
            int gr = row0 + r;
            int gk = k0 + ac;
            bool ok = (gr < M) && (gk + 3 < K);
            const float* src = ok ? (A + (size_t)gr * K + gk) : A;
            cpa16(as_base + buf * asbuf + (r * AS_STRIDE + ac) * 4, src, ok ? 16 : 0);
        }
        {
            int gk = k0 + br;
            int gc = col0 + bc;
            bool ok = (gk < K) && (gc + 3 < N);
            const uint32_t* src = ok ? (B + (size_t)gk * N + gc) : B;
            cpa16(bs_base + buf * bsbuf + (br * BS_STRIDE + bc) * 4, src, ok ? 16 : 0);
        }
        asm volatile("cp.async.commit_group;\n");
    };

    load_tile(0, 0);

    for (int t = 0; t < ntiles; t++) {
        asm volatile("cp.async.wait_group 0;\n");
        __syncthreads();
        if (t + 1 < ntiles) load_tile(t + 1, (t + 1) & 1);
        int buf = t & 1;

#pragma unroll
        for (int ks = 0; ks < 2; ks++) {
            int kb = ks * 8;
            uint32_t afrag[3][4], bfrag[4][2];
#pragma unroll
            for (int mi = 0; mi < 3; mi++) {
                int mrow = warp_m * 48 + mi * 16 + qr;
                afrag[mi][0] = f2tf32(__uint_as_float(As[buf][mrow    ][kb + qc]));
                afrag[mi][1] = f2tf32(__uint_as_float(As[buf][mrow + 8][kb + qc]));
                afrag[mi][2] = f2tf32(__uint_as_float(As[buf][mrow    ][kb + qc + 4]));
                afrag[mi][3] = f2tf32(__uint_as_float(As[buf][mrow + 8][kb + qc + 4]));
            }
#pragma unroll
            for (int nj = 0; nj < 4; nj++) {
                int ncol = warp_n * 32 + nj * 8 + qr;
                bfrag[nj][0] = Bs[buf][kb + qc    ][ncol];
                bfrag[nj][1] = Bs[buf][kb + qc + 4][ncol];
            }
#pragma unroll
            for (int mi = 0; mi < 3; mi++)
#pragma unroll
                for (int nj = 0; nj < 4; nj++) {
                    asm volatile(
                        "mma.sync.aligned.m16n8k8.row.col.f32.tf32.tf32.f32 "
                        "{%0,%1,%2,%3}, {%4,%5,%6,%7}, {%8,%9}, {%0,%1,%2,%3};"
                        : "+f"(c[mi][nj][0]), "+f"(c[mi][nj][1]),
                          "+f"(c[mi][nj][2]), "+f"(c[mi][nj][3])
                        : "r"(afrag[mi][0]), "r"(afrag[mi][1]),
                          "r"(afrag[mi][2]), "r"(afrag[mi][3]),
                          "r"(bfrag[nj][0]), "r"(bfrag[nj][1]));
                }
        }
        __syncthreads();
    }

#pragma unroll
    for (int mi = 0; mi < 3; mi++) {
#pragma unroll
        for (int rh = 0; rh < 2; rh++) {
            int gr = row0 + warp_m * 48 + mi * 16 + rh * 8 + qr;
            if (gr >= M) continue;
#pragma unroll
            for (int nj = 0; nj < 4; nj++) {
#pragma unroll
                for (int jc = 0; jc < 2; jc++) {
                    int gc = col0 + warp_n * 32 + nj * 8 + qc * 2 + jc;
                    if (gc >= N) continue;
                    float v = c[mi][nj][rh * 2 + jc];
                    if (sg.bias) v += sg.bias[gc];
                    if (sg.act) v = fmaxf(v, 0.f);
                    sg.C[(size_t)gr * N + gc] = v;
                }
            }
        }
    }
}

// ---------------- GATv2 layer 1: quad-edge online softmax, emits fp32 h1 ----------------
template <int F>
__global__ __launch_bounds__(256) void gat_agg_kernel(
    const float* __restrict__ xl, const float* __restrict__ xr,
    const float* __restrict__ att, const float* __restrict__ bias,
    const int* __restrict__ ssrc, const int* __restrict__ off,
    float* __restrict__ out)
{
    static_assert(F % 4 == 0, "F must be multiple of 4");
    constexpr int C4 = F / 4;
    constexpr int NJ = (C4 + 31) / 32;
    int warp = (blockIdx.x * blockDim.x + threadIdx.x) >> 5;
    int lane = threadIdx.x & 31;
    if (warp >= NN) return;
    int d = warp;

    float4 xrv[NJ], attv[NJ], acc[NJ];
    bool act[NJ];
#pragma unroll
    for (int j = 0; j < NJ; j++) {
        int cidx = lane + 32 * j;
        act[j] = (cidx < C4);
        float4 zf = make_float4(0.f, 0.f, 0.f, 0.f);
        xrv[j]  = act[j] ? *reinterpret_cast<const float4*>(&xr[(size_t)d * F + 4 * cidx]) : zf;
        attv[j] = act[j] ? *reinterpret_cast<const float4*>(&att[4 * cidx]) : zf;
        acc[j]  = zf;
    }
    int k0 = off[d], k1 = off[d + 1];

    float m = -1e30f, ssum = 0.f;
    const float4 zf4 = make_float4(0.f, 0.f, 0.f, 0.f);

    int k = k0;
    // ---- quad loop ----
    for (; k + 3 < k1; k += 4) {
        int s[4] = { ssrc[k], ssrc[k + 1], ssrc[k + 2], ssrc[k + 3] };
        float4 xs[4][NJ];
#pragma unroll
        for (int e = 0; e < 4; e++) {
            const float4* xp = reinterpret_cast<const float4*>(xl + (size_t)s[e] * F);
#pragma unroll
            for (int j = 0; j < NJ; j++) {
                int cidx = lane + 32 * j;
                xs[e][j] = act[j] ? xp[cidx] : zf4;
            }
        }
        float p[4] = {0.f, 0.f, 0.f, 0.f};
#pragma unroll
        for (int e = 0; e < 4; e++) {
#pragma unroll
            for (int j = 0; j < NJ; j++) {
                float v;
                v = xs[e][j].x + xrv[j].x; v = (v > 0.f) ? v : 0.2f * v; p[e] += v * attv[j].x;
                v = xs[e][j].y + xrv[j].y; v = (v > 0.f) ? v : 0.2f * v; p[e] += v * attv[j].y;
                v = xs[e][j].z + xrv[j].z; v = (v > 0.f) ? v : 0.2f * v; p[e] += v * attv[j].z;
                v = xs[e][j].w + xrv[j].w; v = (v > 0.f) ? v : 0.2f * v; p[e] += v * attv[j].w;
            }
        }
#pragma unroll
        for (int o = 16; o > 0; o >>= 1) {
            p[0] += __shfl_xor_sync(0xffffffffu, p[0], o);
            p[1] += __shfl_xor_sync(0xffffffffu, p[1], o);
            p[2] += __shfl_xor_sync(0xffffffffu, p[2], o);
            p[3] += __shfl_xor_sync(0xffffffffu, p[3], o);
        }
        float mn = fmaxf(fmaxf(m, fmaxf(p[0], p[1])), fmaxf(p[2], p[3]));
        float sc = __expf(m - mn);
        float w0 = __expf(p[0] - mn);
        float w1 = __expf(p[1] - mn);
        float w2 = __expf(p[2] - mn);
        float w3 = __expf(p[3] - mn);
        ssum = ssum * sc + w0 + w1 + w2 + w3;
#pragma unroll
        for (int j = 0; j < NJ; j++) {
            acc[j].x = acc[j].x * sc + w0 * xs[0][j].x + w1 * xs[1][j].x + w2 * xs[2][j].x + w3 * xs[3][j].x;
            acc[j].y = acc[j].y * sc + w0 * xs[0][j].y + w1 * xs[1][j].y + w2 * xs[2][j].y + w3 * xs[3][j].y;
            acc[j].z = acc[j].z * sc + w0 * xs[0][j].z + w1 * xs[1][j].z + w2 * xs[2][j].z + w3 * xs[3][j].z;
            acc[j].w = acc[j].w * sc + w0 * xs[0][j].w + w1 * xs[1][j].w + w2 * xs[2][j].w + w3 * xs[3][j].w;
        }
        m = mn;
    }
    // ---- tail: singles ----
    for (; k < k1; k++) {
        int s = ssrc[k];
        const float4* xar = reinterpret_cast<const float4*>(xl + (size_t)s * F);
        float4 xa[NJ];
#pragma unroll
        for (int j = 0; j < NJ; j++) {
            int cidx = lane + 32 * j;
            xa[j] = act[j] ? xar[cidx] : zf4;
        }
        float p = 0.f;
#pragma unroll
        for (int j = 0; j < NJ; j++) {
            float v;
            v = xa[j].x + xrv[j].x; v = (v > 0.f) ? v : 0.2f * v; p += v * attv[j].x;
            v = xa[j].y + xrv[j].y; v = (v > 0.f) ? v : 0.2f * v; p += v * attv[j].y;
            v = xa[j].z + xrv[j].z; v = (v > 0.f) ? v : 0.2f * v; p += v * attv[j].z;
            v = xa[j].w + xrv[j].w; v = (v > 0.f) ? v : 0.2f * v; p += v * attv[j].w;
        }
#pragma unroll
        for (int o = 16; o > 0; o >>= 1) p += __shfl_xor_sync(0xffffffffu, p, o);
        float mn = fmaxf(m, p);
        float sc = __expf(m - mn);
        float w  = __expf(p - mn);
        ssum = ssum * sc + w;
#pragma unroll
        for (int j = 0; j < NJ; j++) {
            acc[j].x = acc[j].x * sc + w * xa[j].x;
            acc[j].y = acc[j].y * sc + w * xa[j].y;
            acc[j].z = acc[j].z * sc + w * xa[j].z;
            acc[j].w = acc[j].w * sc + w * xa[j].w;
        }
        m = mn;
    }

    float inv = 1.f / (ssum + 1e-16f);
#pragma unroll
    for (int j = 0; j < NJ; j++) {
        int cidx = lane + 32 * j;
        if (!act[j]) continue;
        float4 bv = *reinterpret_cast<const float4*>(&bias[4 * cidx]);
        float4 o;
        o.x = fmaxf(acc[j].x * inv + bv.x, 0.f);
        o.y = fmaxf(acc[j].y * inv + bv.y, 0.f);
        o.z = fmaxf(acc[j].z * inv + bv.z, 0.f);
        o.w = fmaxf(acc[j].w * inv + bv.w, 0.f);
        *reinterpret_cast<float4*>(&out[(size_t)d * F + 4 * cidx]) = o;
    }
}

// ---------------- GATv2 layer 2 (F=100), quad-edge, fused epilogue ----------------
__global__ __launch_bounds__(256) void gat_agg100_fused(
    const float* __restrict__ xl, const float* __restrict__ xr,
    const float* __restrict__ att, const float* __restrict__ bias,
    const int* __restrict__ ssrc, const int* __restrict__ off,
    const float* __restrict__ lin1, const float* __restrict__ lin2,
    const float* __restrict__ Wl3, const float* __restrict__ Wr3,
    uint32_t* __restrict__ zb, float* __restrict__ xl3, float* __restrict__ xr3)
{
    int warp = (blockIdx.x * blockDim.x + threadIdx.x) >> 5;
    int lane = threadIdx.x & 31;
    if (warp >= NN) return;
    int d = warp;
    bool on = (lane < 25);    // 25 float4 chunks cover F=100

    float4 zf = make_float4(0.f, 0.f, 0.f, 0.f);
    float4 xrv = on ? *reinterpret_cast<const float4*>(&xr[(size_t)d * 100 + 4 * lane]) : zf;
    float4 attv = on ? *reinterpret_cast<const float4*>(&att[4 * lane]) : zf;
    float4 acc = zf;
    int k0 = off[d], k1 = off[d + 1];

    float m = -1e30f, ssum = 0.f;

    int k = k0;
    // ---- quad loop ----
    for (; k + 3 < k1; k += 4) {
        int s[4] = { ssrc[k], ssrc[k + 1], ssrc[k + 2], ssrc[k + 3] };
        float4 xs[4];
#pragma unroll
        for (int e = 0; e < 4; e++)
            xs[e] = on ? *reinterpret_cast<const float4*>(&xl[(size_t)s[e] * 100 + 4 * lane]) : zf;
        float p[4] = {0.f, 0.f, 0.f, 0.f};
#pragma unroll
        for (int e = 0; e < 4; e++) {
            float v;
            v = xs[e].x + xrv.x; v = (v > 0.f) ? v : 0.2f * v; p[e] += v * attv.x;
            v = xs[e].y + xrv.y; v = (v > 0.f) ? v : 0.2f * v; p[e] += v * attv.y;
            v = xs[e].z + xrv.z; v = (v > 0.f) ? v : 0.2f * v; p[e] += v * attv.z;
            v = xs[e].w + xrv.w; v = (v > 0.f) ? v : 0.2f * v; p[e] += v * attv.w;
        }
#pragma unroll
        for (int o = 16; o > 0; o >>= 1) {
            p[0] += __shfl_xor_sync(0xffffffffu, p[0], o);
            p[1] += __shfl_xor_sync(0xffffffffu, p[1], o);
            p[2] += __shfl_xor_sync(0xffffffffu, p[2], o);
            p[3] += __shfl_xor_sync(0xffffffffu, p[3], o);
        }
        float mn = fmaxf(fmaxf(m, fmaxf(p[0], p[1])), fmaxf(p[2], p[3]));
        float sc = __expf(m - mn);
        float w0 = __expf(p[0] - mn);
        float w1 = __expf(p[1] - mn);
        float w2 = __expf(p[2] - mn);
        float w3 = __expf(p[3] - mn);
        ssum = ssum * sc + w0 + w1 + w2 + w3;
        acc.x = acc.x * sc + w0 * xs[0].x + w1 * xs[1].x + w2 * xs[2].x + w3 * xs[3].x;
        acc.y = acc.y * sc + w0 * xs[0].y + w1 * xs[1].y + w2 * xs[2].y + w3 * xs[3].y;
        acc.z = acc.z * sc + w0 * xs[0].z + w1 * xs[1].z + w2 * xs[2].z + w3 * xs[3].z;
        acc.w = acc.w * sc + w0 * xs[0].w + w1 * xs[1].w + w2 * xs[2].w + w3 * xs[3].w;
        m = mn;
    }
    // ---- tail: singles ----
    for (; k < k1; k++) {
        int s = ssrc[k];
        float4 xa = on ? *reinterpret_cast<const float4*>(&xl[(size_t)s * 100 + 4 * lane]) : zf;
        float p = 0.f, v;
        v = xa.x + xrv.x; v = (v > 0.f) ? v : 0.2f * v; p += v * attv.x;
        v = xa.y + xrv.y; v = (v > 0.f) ? v : 0.2f * v; p += v * attv.y;
        v = xa.z + xrv.z; v = (v > 0.f) ? v : 0.2f * v; p += v * attv.z;
        v = xa.w + xrv.w; v = (v > 0.f) ? v : 0.2f * v; p += v * attv.w;
#pragma unroll
        for (int o = 16; o > 0; o >>= 1) p += __shfl_xor_sync(0xffffffffu, p, o);
        float mn = fmaxf(m, p);
        float sc = __expf(m - mn);
        float w  = __expf(p - mn);
        ssum = ssum * sc + w;
        acc.x = acc.x * sc + w * xa.x;
        acc.y = acc.y * sc + w * xa.y;
        acc.z = acc.z * sc + w * xa.z;
        acc.w = acc.w * sc + w * xa.w;
        m = mn;
    }

    float inv = 1.f / (ssum + 1e-16f);
    float pl = 0.f, pr = 0.f;
    if (on) {
        float4 bv = *reinterpret_cast<const float4*>(&bias[4 * lane]);
        float4 h;
        h.x = fmaxf(acc.x * inv + bv.x, 0.f);
        h.y = fmaxf(acc.y * inv + bv.y, 0.f);
        h.z = fmaxf(acc.z * inv + bv.z, 0.f);
        h.w = fmaxf(acc.w * inv + bv.w, 0.f);
        float4 l1 = *reinterpret_cast<const float4*>(&lin1[(size_t)d * 100 + 4 * lane]);
        float4 l2 = *reinterpret_cast<const float4*>(&lin2[(size_t)d * 100 + 4 * lane]);
        float4 xo4, z4;
        xo4.x = h.x + l1.x; xo4.y = h.y + l1.y; xo4.z = h.z + l1.z; xo4.w = h.w + l1.w;
        z4.x  = h.x + l2.x; z4.y  = h.y + l2.y; z4.z  = h.z + l2.z; z4.w  = h.w + l2.w;
        // z as bf16x2 pairs (consumed only by the loss kernel)
        uint2 zp;
        zp.x = pack_bf16x2(z4.x, z4.y);
        zp.y = pack_bf16x2(z4.z, z4.w);
        *reinterpret_cast<uint2*>(&zb[(size_t)d * 50 + 2 * lane]) = zp;
        float4 wl = *reinterpret_cast<const float4*>(&Wl3[4 * lane]);
        float4 wr = *reinterpret_cast<const float4*>(&Wr3[4 * lane]);
        pl = xo4.x * wl.x + xo4.y * wl.y + xo4.z * wl.z + xo4.w * wl.w;
        pr = xo4.x * wr.x + xo4.y * wr.y + xo4.z * wr.z + xo4.w * wr.w;
    }
#pragma unroll
    for (int o = 16; o > 0; o >>= 1) {
        pl += __shfl_xor_sync(0xffffffffu, pl, o);
        pr += __shfl_xor_sync(0xffffffffu, pr, o);
    }
    if (lane == 0) { xl3[d] = pl; xr3[d] = pr; }
}

// ---------------- layer-3 GAT (F=1) ----------------
__global__ __launch_bounds__(256) void gat3_kernel(
    const float* __restrict__ xl3, const float* __restrict__ xr3,
    const float* __restrict__ att3, const float* __restrict__ b3,
    const int* __restrict__ ssrc, const int* __restrict__ off,
    float* __restrict__ out)
{
    int warp = (blockIdx.x * blockDim.x + threadIdx.x) >> 5;
    int lane = threadIdx.x & 31;
    if (warp >= NN) return;
    int d = warp;
    float a0 = att3[0];
    float xrd = xr3[d];
    int k0 = off[d], k1 = off[d + 1];

    float m = -1e30f;
    for (int k = k0 + lane; k < k1; k += 32) {
        float v = xl3[ssrc[k]] + xrd;
        v = (v > 0.f) ? v : 0.2f * v;
        m = fmaxf(m, v * a0);
    }
#pragma unroll
    for (int o = 16; o > 0; o >>= 1) m = fmaxf(m, __shfl_xor_sync(0xffffffffu, m, o));

    float ssum = 0.f, acc = 0.f;
    for (int k = k0 + lane; k < k1; k += 32) {
        float xs = xl3[ssrc[k]];
        float v = xs + xrd;
        v = (v > 0.f) ? v : 0.2f * v;
        float w = __expf(v * a0 - m);
        ssum += w;
        acc  += w * xs;
    }
#pragma unroll
    for (int o = 16; o > 0; o >>= 1) {
        ssum += __shfl_xor_sync(0xffffffffu, ssum, o);
        acc  += __shfl_xor_sync(0xffffffffu, acc, o);
    }
    if (lane == 0) out[d] = acc / (ssum + 1e-16f) + b3[0];
}

// ---------------- link-prediction loss: bf16 z, paired edges ----------------
__global__ void loss_kernel(const uint32_t* __restrict__ zb, const int* __restrict__ ei,
                            const int* __restrict__ nei, float* __restrict__ accum) {
    int half = gridDim.x >> 1;
    int positive = (blockIdx.x < half) ? 1 : 0;
    int bid = positive ? blockIdx.x : (blockIdx.x - half);
    const int* ea = positive ? ei : nei;
    const int* eb = positive ? (ei + EE) : (nei + EE);

    int warp = (bid * blockDim.x + threadIdx.x) >> 5;
    int lane = threadIdx.x & 31;
    int nwarps = (half * blockDim.x) >> 5;
    float local = 0.f;
    for (int e = warp * 2; e + 1 < EE; e += 2 * nwarps) {
        int a0 = ea[e],     b0 = eb[e];
        int a1 = ea[e + 1], b1 = eb[e + 1];
        float p0 = 0.f, p1 = 0.f;
        if (lane < 25) {
            uint2 va0 = *reinterpret_cast<const uint2*>(&zb[(size_t)a0 * 50 + lane * 2]);
            uint2 vb0 = *reinterpret_cast<const uint2*>(&zb[(size_t)b0 * 50 + lane * 2]);
            uint2 va1 = *reinterpret_cast<const uint2*>(&zb[(size_t)a1 * 50 + lane * 2]);
            uint2 vb1 = *reinterpret_cast<const uint2*>(&zb[(size_t)b1 * 50 + lane * 2]);
            p0 += bf16lo(va0.x) * bf16lo(vb0.x) + bf16hi(va0.x) * bf16hi(vb0.x);
            p0 += bf16lo(va0.y) * bf16lo(vb0.y) + bf16hi(va0.y) * bf16hi(vb0.y);
            p1 += bf16lo(va1.x) * bf16lo(vb1.x) + bf16hi(va1.x) * bf16hi(vb1.x);
            p1 += bf16lo(va1.y) * bf16lo(vb1.y) + bf16hi(va1.y) * bf16hi(vb1.y);
        }
#pragma unroll
        for (int o = 16; o > 0; o >>= 1) {
            p0 += __shfl_xor_sync(0xffffffffu, p0, o);
            p1 += __shfl_xor_sync(0xffffffffu, p1, o);
        }
        if (lane == 0) {
            float s0 = 1.f / (1.f + __expf(-p0));
            float s1 = 1.f / (1.f + __expf(-p1));
            if (positive) local += __logf(s0 + 1e-15f) + __logf(s1 + 1e-15f);
            else          local += __logf(1.f - s0 + 1e-15f) + __logf(1.f - s1 + 1e-15f);
        }
    }
    if (lane == 0) atomicAdd(&accum[positive ? 0 : 1], local);
}

__global__ void finalize_kernel(float* __restrict__ d_out, const float* __restrict__ loss,
                                const float* __restrict__ c1, const float* __restrict__ c2) {
    if (threadIdx.x == 0) {
        d_out[NN]     = -(loss[0] + loss[1]) / (float)EE;
        d_out[NN + 1] = c1[0];
        d_out[NN + 2] = c2[0];
    }
}

// ---------------- launch ----------------
extern "C" void kernel_launch(void* const* d_in, const int* in_sizes, int n_in,
                              void* d_out, int out_size) {
    const float* x     = (const float*)d_in[0];
    const int*   ei    = (const int*)  d_in[1];
    const int*   nei   = (const int*)  d_in[2];
    const float* Wl1   = (const float*)d_in[3];
    const float* Wr1   = (const float*)d_in[4];
    const float* att1  = (const float*)d_in[5];
    const float* b1    = (const float*)d_in[6];
    const float* Wl2   = (const float*)d_in[7];
    const float* Wr2   = (const float*)d_in[8];
    const float* att2  = (const float*)d_in[9];
    const float* b2    = (const float*)d_in[10];
    const float* Wl3   = (const float*)d_in[11];
    const float* Wr3   = (const float*)d_in[12];
    const float* att3  = (const float*)d_in[13];
    const float* b3    = (const float*)d_in[14];
    const float* Wlin1 = (const float*)d_in[15];
    const float* blin1 = (const float*)d_in[16];
    const float* Wlin2 = (const float*)d_in[17];
    const float* blin2 = (const float*)d_in[18];
    const float* c1    = (const float*)d_in[19];
    const float* c2    = (const float*)d_in[20];
    float* out = (float*)d_out;

    uint32_t *wtf, *zb;
    float *h1, *xl1, *xr1, *xl2, *xr2, *lin1, *lin2, *xl3, *xr3, *loss;
    int *deg, *off, *cur, *ssrc;
    cudaGetSymbolAddress((void**)&h1,   g_h1);
    cudaGetSymbolAddress((void**)&wtf,  g_wtf);
    cudaGetSymbolAddress((void**)&xl1,  g_xl1);
    cudaGetSymbolAddress((void**)&xr1,  g_xr1);
    cudaGetSymbolAddress((void**)&xl2,  g_xl2);
    cudaGetSymbolAddress((void**)&xr2,  g_xr2);
    cudaGetSymbolAddress((void**)&lin1, g_lin1);
    cudaGetSymbolAddress((void**)&lin2, g_lin2);
    cudaGetSymbolAddress((void**)&zb,   g_zb);
    cudaGetSymbolAddress((void**)&xl3,  g_xl3);
    cudaGetSymbolAddress((void**)&xr3,  g_xr3);
    cudaGetSymbolAddress((void**)&loss, g_loss);
    cudaGetSymbolAddress((void**)&deg,  g_deg);
    cudaGetSymbolAddress((void**)&off,  g_off);
    cudaGetSymbolAddress((void**)&cur,  g_cur);
    cudaGetSymbolAddress((void**)&ssrc, g_src);

    // side streams + fork/join events (capturable pattern)
    cudaStream_t sCsr, sLin, sLoss;
    cudaStreamCreateWithFlags(&sCsr,  cudaStreamNonBlocking);
    cudaStreamCreateWithFlags(&sLin,  cudaStreamNonBlocking);
    cudaStreamCreateWithFlags(&sLoss, cudaStreamNonBlocking);
    cudaEvent_t evRoot, evCsr, evConv, evLin, evMid, evLoss;
    cudaEventCreateWithFlags(&evRoot, cudaEventDisableTiming);
    cudaEventCreateWithFlags(&evCsr,  cudaEventDisableTiming);
    cudaEventCreateWithFlags(&evConv, cudaEventDisableTiming);
    cudaEventCreateWithFlags(&evLin,  cudaEventDisableTiming);
    cudaEventCreateWithFlags(&evMid,  cudaEventDisableTiming);
    cudaEventCreateWithFlags(&evLoss, cudaEventDisableTiming);

    // ---- fork: CSR build on side stream (depends only on ei) ----
    cudaEventRecord(evRoot, 0);
    cudaStreamWaitEvent(sCsr, evRoot, 0);
    zero_kernel<<<(NN + 255) / 256, 256, 0, sCsr>>>(deg, cur, loss);
    hist_kernel<<<(E2T + 255) / 256, 256, 0, sCsr>>>(ei, deg);
    scan_kernel<<<1, 1024, 0, sCsr>>>(deg, off);
    scatter_kernel<<<(E2T + 255) / 256, 256, 0, sCsr>>>(ei, cur, off, ssrc);
    cudaEventRecord(evCsr, sCsr);

    // ---- main: weight tf32 conversion (tiny; x stays fp32) ----
    {
        CSeg c0 = { Wl1,   wtf + OFF_WL1,   150000 / 4 };
        CSeg c1s= { Wr1,   wtf + OFF_WR1,   150000 / 4 };
        CSeg c2s= { Wlin1, wtf + OFF_WLIN1, 50000 / 4 };
        CSeg c3 = { Wlin2, wtf + OFF_WLIN2, 50000 / 4 };
        CSeg c4 = { Wl2,   wtf + OFF_WL2,   30000 / 4 };
        CSeg c5 = { Wr2,   wtf + OFF_WR2,   30000 / 4 };
        conv_weights<<<(150000 / 4 + 255) / 256, 256>>>(c0, c1s, c2s, c3, c4, c5);
    }
    cudaEventRecord(evConv, 0);

    dim3 tb(256);
    int rows = (NN + BM - 1) / BM;   // 71

    // ---- fork: skip-linear GEMM on side stream (needed only at agg100_fused) ----
    cudaStreamWaitEvent(sLin, evConv, 0);
    {
        GSeg s0 = { wtf + OFF_WLIN1, blin1, lin1, 100, 1, 0 };
        GSeg s1 = { wtf + OFF_WLIN2, blin2, lin2, 100, 1, 2 };
        gemm_tf32_multi<<<dim3(4, rows), tb, 0, sLin>>>(x, NN, 500, s0, s1, s0, s1, 2);
    }
    cudaEventRecord(evLin, sLin);

    // ---- main: layer-1 attention projections (A = x fp32, cvt in-kernel) ----
    {
        GSeg s0 = { wtf + OFF_WL1, nullptr, xl1, 300, 0, 0 };
        GSeg s1 = { wtf + OFF_WR1, nullptr, xr1, 300, 0, 5 };
        gemm_tf32_multi<<<dim3(10, rows), tb>>>(x, NN, 500, s0, s1, s0, s1, 2);
    }

    // ---- join CSR, then edge phase ----
    cudaStreamWaitEvent(0, evCsr, 0);
    int agg_blocks = (NN + 7) / 8;
    gat_agg_kernel<300><<<agg_blocks, 256>>>(xl1, xr1, att1, b1, ssrc, off, h1);

    {
        GSeg s0 = { wtf + OFF_WL2, nullptr, xl2, 100, 0, 0 };
        GSeg s1 = { wtf + OFF_WR2, nullptr, xr2, 100, 0, 2 };
        gemm_tf32_multi<<<dim3(4, rows), tb>>>(h1, NN, 300, s0, s1, s0, s1, 2);
    }

    // join the skip-linear GEMM before the fused layer-2 aggregation
    cudaStreamWaitEvent(0, evLin, 0);
    gat_agg100_fused<<<agg_blocks, 256>>>(xl2, xr2, att2, b2, ssrc, off,
                                          lin1, lin2, Wl3, Wr3, zb, xl3, xr3);

    // ---- fork: loss on side stream, gat3 on main ----
    cudaEventRecord(evMid, 0);
    cudaStreamWaitEvent(sLoss, evMid, 0);
    loss_kernel<<<4096, 256, 0, sLoss>>>(zb, ei, nei, loss);
    cudaEventRecord(evLoss, sLoss);

    gat3_kernel<<<agg_blocks, 256>>>(xl3, xr3, att3, b3, ssrc, off, out);

    cudaStreamWaitEvent(0, evLoss, 0);
    finalize_kernel<<<1, 32>>>(out, loss, c1, c2);

    cudaEventDestroy(evRoot);
    cudaEventDestroy(evCsr);
    cudaEventDestroy(evConv);
    cudaEventDestroy(evLin);
    cudaEventDestroy(evMid);
    cudaEventDestroy(evLoss);
    cudaStreamDestroy(sCsr);
    cudaStreamDestroy(sLin);
    cudaStreamDestroy(sLoss);
}